// round 1
// baseline (speedup 1.0000x reference)
#include <cuda_runtime.h>
#include <cuda_fp16.h>

#define BATCH 4
#define NNODE 4096
#define DIM   256
#define OUTC  64
#define NPAD  72          // 64 cols + e column (64) + 7 zero pad -> 9 n-tiles of 8
#define NT    9
#define KSPLIT 4
#define KCH   128         // k-chunk staged per __syncthreads in GEMM

// ---------------- device scratch (static: no allocations allowed) ----------------
__device__ float g_vsrc[DIM];
__device__ float g_WT[DIM * OUTC];          // [d][l]  (Wsum transposed)
__device__ float g_bsum[OUTC];
__device__ float g_src[BATCH * NNODE];
__device__ float g_m[BATCH];
// P in mma-B-fragment layout: [chunk(=flatrow/16)][ntile][lane] -> uint2 (4 halves)
__device__ uint2 g_Pfrag[(BATCH * NNODE / 16) * NT * 32];
// split-K partials: [kz][b][i][NPAD]
__device__ float g_Cp[(size_t)KSPLIT * BATCH * NNODE * NPAD];

// ---------------- helpers ----------------
__device__ __forceinline__ unsigned int f2_to_h2(float2 f) {
    __half2 h = __float22half2_rn(f);      // f.x -> low 16 bits (lower k index)
    return *reinterpret_cast<unsigned int*>(&h);
}

// ---------------- kernel A: weight preprocessing (tiny) ----------------
__global__ void k_prep(const float* __restrict__ Wfc,
                       const float* __restrict__ bfc,
                       const float* __restrict__ Wattn) {
    __shared__ float wsrc[DIM];
    int t = threadIdx.x;                    // 256 threads
    int h = t >> 6, o = t & 63;
    float s = 0.f;
    #pragma unroll
    for (int k = 0; k < 4; k++) s += Wattn[k * 512 + h * 128 + o];
    wsrc[t] = 0.25f * s;
    __syncthreads();
    // v_src[d] = sum_m wsrc[m] * Wfc[m][d]
    float v = 0.f;
    for (int m = 0; m < DIM; m++) v += wsrc[m] * Wfc[m * DIM + t];
    g_vsrc[t] = v;
    // WT[d][l] = sum_h Wfc[h*64+l][d]
    for (int l = 0; l < OUTC; l++) {
        float a = 0.f;
        #pragma unroll
        for (int hh = 0; hh < 4; hh++) a += Wfc[(hh * 64 + l) * DIM + t];
        g_WT[t * OUTC + l] = a;
    }
    if (t < OUTC) {
        float a = 0.f;
        #pragma unroll
        for (int hh = 0; hh < 4; hh++) a += bfc[hh * 64 + t];
        g_bsum[t] = a;
    }
}

// ---------------- kernel B: src[b,j] = X . v_src ----------------
__global__ void k_src(const float* __restrict__ X) {
    int warp = threadIdx.x >> 5, lane = threadIdx.x & 31;
    int row = blockIdx.x * 8 + warp;        // [0, 16384)
    const float* xr = X + (size_t)row * DIM;
    float s = 0.f;
    #pragma unroll
    for (int q = 0; q < 8; q++) s += xr[lane + 32 * q] * g_vsrc[lane + 32 * q];
    #pragma unroll
    for (int o = 16; o; o >>= 1) s += __shfl_xor_sync(0xffffffffu, s, o);
    if (lane == 0) g_src[row] = s;
}

// ---------------- kernel C: per-batch max of src ----------------
__global__ void k_max() {
    __shared__ float red[256];
    int b = blockIdx.x, t = threadIdx.x;
    float m = -1e30f;
    for (int j = t; j < NNODE; j += 256) m = fmaxf(m, g_src[b * NNODE + j]);
    red[t] = m;
    __syncthreads();
    for (int s = 128; s; s >>= 1) {
        if (t < s) red[t] = fmaxf(red[t], red[t + s]);
        __syncthreads();
    }
    if (t == 0) g_m[b] = red[0];
}

// ---------------- kernel D: build P (e*h_sum | e | 0-pad) in fragment layout ----------------
#define DROWS 32
__global__ void __launch_bounds__(256) k_p(const float* __restrict__ X) {
    __shared__ float Xs[DROWS][DIM];        // 32 KB
    __shared__ __half Ps[DROWS][NPAD];      // 4.5 KB
    __shared__ float es[DROWS];
    int t = threadIdx.x;
    int row0 = blockIdx.x * DROWS;          // flat row over B*N
    int b = row0 >> 12;

    const float4* xsrc = (const float4*)(X + (size_t)row0 * DIM);
    float4* xdst = (float4*)&Xs[0][0];
    for (int i = t; i < DROWS * DIM / 4; i += 256) xdst[i] = xsrc[i];
    if (t < DROWS) es[t] = expf(g_src[row0 + t] - g_m[b]);
    __syncthreads();

    int l = t & 63, rg = t >> 6;            // rg: 0..3 -> rows rg*8..rg*8+7
    float acc[8];
    #pragma unroll
    for (int r = 0; r < 8; r++) acc[r] = 0.f;
    for (int d = 0; d < DIM; d += 4) {
        float w0 = g_WT[(d + 0) * OUTC + l];
        float w1 = g_WT[(d + 1) * OUTC + l];
        float w2 = g_WT[(d + 2) * OUTC + l];
        float w3 = g_WT[(d + 3) * OUTC + l];
        #pragma unroll
        for (int r = 0; r < 8; r++) {
            const float4 xv = *(const float4*)&Xs[rg * 8 + r][d];
            acc[r] += xv.x * w0 + xv.y * w1 + xv.z * w2 + xv.w * w3;
        }
    }
    float bs = g_bsum[l];
    #pragma unroll
    for (int r = 0; r < 8; r++) {
        int rr = rg * 8 + r;
        Ps[rr][l] = __float2half(es[rr] * (acc[r] + bs));
    }
    {   // columns 64..71: e in 64, zeros elsewhere (256 threads cover 32x8)
        int rr = t >> 3, c = 64 + (t & 7);
        Ps[rr][c] = (c == 64) ? __float2half(es[rr]) : __float2half(0.f);
    }
    __syncthreads();

    // repack into mma B-fragment layout: 2 k-chunks x 9 ntiles x 32 lanes
    for (int idx = t; idx < 2 * NT * 32; idx += 256) {
        int kc = idx / (NT * 32);
        int rem = idx - kc * NT * 32;
        int nt = rem >> 5, lane = rem & 31;
        int g = lane >> 2, tg = lane & 3;
        int jl = kc * 16 + tg * 2, n = nt * 8 + g;
        uint2 v;
        v.x = (unsigned int)__half_as_ushort(Ps[jl][n]) |
              ((unsigned int)__half_as_ushort(Ps[jl + 1][n]) << 16);
        v.y = (unsigned int)__half_as_ushort(Ps[jl + 8][n]) |
              ((unsigned int)__half_as_ushort(Ps[jl + 9][n]) << 16);
        int chunk = row0 / 16 + kc;         // flat chunk id == b*256 + k/16
        g_Pfrag[((size_t)chunk * NT + nt) * 32 + lane] = v;
    }
}

// ---------------- kernel E: C[b,i,:] = adj[b,i,:] @ P  (split-K, fp16 MMA) ----------------
__global__ void __launch_bounds__(128) k_gemm(const float* __restrict__ adj) {
    __shared__ uint2 Bs[KCH / 16][NT][32];  // 18 KB
    int t = threadIdx.x, lane = t & 31, warp = t >> 5;
    int b = blockIdx.y, kz = blockIdx.z;
    int i0 = blockIdx.x * 64 + warp * 16;
    int g = lane >> 2, tg = lane & 3;

    const float* a0p = adj + ((size_t)b * NNODE + i0 + g) * NNODE;
    const float* a1p = adj + ((size_t)b * NNODE + i0 + g + 8) * NNODE;

    float acc[NT][4];
    #pragma unroll
    for (int nt = 0; nt < NT; nt++)
        #pragma unroll
        for (int q = 0; q < 4; q++) acc[nt][q] = 0.f;

    const int KLEN = NNODE / KSPLIT;        // 1024
    int kbase = kz * KLEN;

    for (int kb = 0; kb < KLEN; kb += KCH) {
        const uint2* bsrc =
            g_Pfrag + (size_t)(b * (NNODE / 16) + (kbase + kb) / 16) * NT * 32;
        uint2* bdst = &Bs[0][0][0];
        for (int i = t; i < (KCH / 16) * NT * 32; i += 128) bdst[i] = bsrc[i];
        __syncthreads();

        #pragma unroll
        for (int ks = 0; ks < KCH / 16; ks++) {
            int k0 = kbase + kb + ks * 16 + tg * 2;
            float2 f00 = *(const float2*)(a0p + k0);
            float2 f10 = *(const float2*)(a1p + k0);
            float2 f01 = *(const float2*)(a0p + k0 + 8);
            float2 f11 = *(const float2*)(a1p + k0 + 8);
            unsigned int A0 = f2_to_h2(f00);
            unsigned int A1 = f2_to_h2(f10);
            unsigned int A2 = f2_to_h2(f01);
            unsigned int A3 = f2_to_h2(f11);
            #pragma unroll
            for (int nt = 0; nt < NT; nt++) {
                uint2 bb = Bs[ks][nt][lane];
                asm volatile(
                    "mma.sync.aligned.m16n8k16.row.col.f32.f16.f16.f32 "
                    "{%0,%1,%2,%3}, {%4,%5,%6,%7}, {%8,%9}, {%0,%1,%2,%3};\n"
                    : "+f"(acc[nt][0]), "+f"(acc[nt][1]),
                      "+f"(acc[nt][2]), "+f"(acc[nt][3])
                    : "r"(A0), "r"(A1), "r"(A2), "r"(A3), "r"(bb.x), "r"(bb.y));
            }
        }
        __syncthreads();
    }

    size_t base = (((size_t)kz * BATCH + b) * NNODE + i0 + g) * NPAD;
    #pragma unroll
    for (int nt = 0; nt < NT; nt++) {
        int c = nt * 8 + tg * 2;
        *(float2*)&g_Cp[base + c] = make_float2(acc[nt][0], acc[nt][1]);
        *(float2*)&g_Cp[base + (size_t)8 * NPAD + c] =
            make_float2(acc[nt][2], acc[nt][3]);
    }
}

// ---------------- kernel F: reduce split-K, divide by (den * N) ----------------
__global__ void k_out(float* __restrict__ out) {
    int idx = blockIdx.x * 256 + threadIdx.x;   // < 4*4096*64
    int l = idx & 63;
    int rowflat = idx >> 6;                     // b*4096 + i
    float num = 0.f, den = 0.f;
    #pragma unroll
    for (int z = 0; z < KSPLIT; z++) {
        size_t base = ((size_t)z * BATCH * NNODE + rowflat) * NPAD;
        num += g_Cp[base + l];
        den += g_Cp[base + 64];
    }
    out[idx] = num / (den * (float)NNODE);
}

// ---------------- launch ----------------
extern "C" void kernel_launch(void* const* d_in, const int* in_sizes, int n_in,
                              void* d_out, int out_size) {
    const float* X     = (const float*)d_in[0];   // features [4,4096,256]
    const float* adj   = (const float*)d_in[1];   // adj      [4,4096,4096]
    const float* Wfc   = (const float*)d_in[2];   // [256,256]
    const float* bfc   = (const float*)d_in[3];   // [256]
    const float* Wattn = (const float*)d_in[4];   // [4,512]
    float* out = (float*)d_out;                   // [4,4096,64]
    (void)in_sizes; (void)n_in; (void)out_size;   // b_attn (d_in[5]) cancels in softmax

    k_prep<<<1, 256>>>(Wfc, bfc, Wattn);
    k_src<<<BATCH * NNODE / 8, 256>>>(X);
    k_max<<<BATCH, 256>>>();
    k_p<<<BATCH * NNODE / DROWS, 256>>>(X);
    dim3 ge(NNODE / 64, BATCH, KSPLIT);
    k_gemm<<<ge, 128>>>(adj);
    k_out<<<BATCH * NNODE * OUTC / 256, 256>>>(out);
}